// round 1
// baseline (speedup 1.0000x reference)
#include <cuda_runtime.h>
#include <cuda_bf16.h>
#include <cstdint>
#include <cstdio>

// Problem dims (fixed)
#define B 64
#define S 2048
#define I 256
#define H 256
#define O 256
#define IH 512          // I+H
#define G3 768          // 3*H gates
#define NROWS (B*S)     // 131072

// ---------------- scratch (static device globals; allocation-free) ----------
__device__ float g_gx[(size_t)B * S * G3];   // [B][S][768] x-part of gate preacts (+bias)
__device__ float g_hs[(size_t)B * S * H];    // [B][S][256] hidden states
__device__ float g_Wx[G3 * I];               // packed x-part weights [768][256]
__device__ float g_bx[G3];                   // packed biases

// ---------------- weight pack kernel ----------------------------------------
__global__ void pack_weights(const float* __restrict__ Wr, const float* __restrict__ Wz,
                             const float* __restrict__ Wh, const float* __restrict__ br,
                             const float* __restrict__ bz, const float* __restrict__ bh)
{
    int m = blockIdx.x;               // 0..767  (gate*256 + dim)
    int d = m & 255;
    const float* Wsrc = (m < 256) ? Wr : (m < 512 ? Wz : Wh);
    for (int k = threadIdx.x; k < I; k += blockDim.x)
        g_Wx[m * I + k] = Wsrc[(size_t)d * IH + k];     // x-columns [0,256)
    if (threadIdx.x == 0)
        g_bx[m] = (m < 256 ? br : (m < 512 ? bz : bh))[d];
}

// ---------------- fp32 tiled GEMM: C[n][m] = sum_k A[n][k]*W[m][k] + bias[m] -
// K = 256 fixed. BM=128, BN=64, 256 threads, 8x4 microtile.
__global__ void __launch_bounds__(256)
gemm_bias(const float* __restrict__ A, const float* __restrict__ W,
          const float* __restrict__ bias, float* __restrict__ C, int M)
{
    __shared__ float As[16][128];
    __shared__ float Bs[16][68];

    const int n0 = blockIdx.x * 128;
    const int m0 = blockIdx.y * 64;
    const int t  = threadIdx.x;
    const int tx = t & 15;       // col group
    const int ty = t >> 4;       // row group

    float acc[8][4];
#pragma unroll
    for (int i = 0; i < 8; i++)
#pragma unroll
        for (int j = 0; j < 4; j++) acc[i][j] = 0.f;

    for (int k0 = 0; k0 < 256; k0 += 16) {
        // load A tile (128 x 16), transposed into As[k][n]
#pragma unroll
        for (int i = 0; i < 2; i++) {
            int idx = t + i * 256;
            int r = idx & 127, kg = idx >> 7;
            float4 v = *(const float4*)(A + (size_t)(n0 + r) * 256 + k0 + kg * 4);
            As[kg * 4 + 0][r] = v.x;
            As[kg * 4 + 1][r] = v.y;
            As[kg * 4 + 2][r] = v.z;
            As[kg * 4 + 3][r] = v.w;
        }
        // load W tile (64 x 16), transposed into Bs[k][m]
        {
            int r = t & 63, kg = t >> 6;
            float4 v = *(const float4*)(W + (size_t)(m0 + r) * 256 + k0 + kg * 4);
            Bs[kg * 4 + 0][r] = v.x;
            Bs[kg * 4 + 1][r] = v.y;
            Bs[kg * 4 + 2][r] = v.z;
            Bs[kg * 4 + 3][r] = v.w;
        }
        __syncthreads();
#pragma unroll
        for (int kk = 0; kk < 16; kk++) {
            float a[8], bb[4];
#pragma unroll
            for (int i = 0; i < 8; i++) a[i] = As[kk][ty * 8 + i];
#pragma unroll
            for (int j = 0; j < 4; j++) bb[j] = Bs[kk][tx * 4 + j];
#pragma unroll
            for (int i = 0; i < 8; i++)
#pragma unroll
                for (int j = 0; j < 4; j++) acc[i][j] += a[i] * bb[j];
        }
        __syncthreads();
    }

    float b0 = bias[m0 + tx * 4 + 0];
    float b1 = bias[m0 + tx * 4 + 1];
    float b2 = bias[m0 + tx * 4 + 2];
    float b3 = bias[m0 + tx * 4 + 3];
#pragma unroll
    for (int i = 0; i < 8; i++) {
        int n = n0 + ty * 8 + i;
        float4 o;
        o.x = acc[i][0] + b0;
        o.y = acc[i][1] + b1;
        o.z = acc[i][2] + b2;
        o.w = acc[i][3] + b3;
        *(float4*)(C + (size_t)n * M + m0 + tx * 4) = o;
    }
}

// ---------------- recurrent kernel ------------------------------------------
// 16 clusters x 8 CTAs. Cluster c handles batches [4c, 4c+4).
// CTA rank j owns hidden dims [32j, 32j+32) (computes r,z,htilde,h for them).
// Weights (h-part of W_r/W_z/W_h for own dims) cached in SMEM (~98KB/CTA).
// Full h and r*h vectors replicated per CTA via DSMEM remote stores.
#define WSTR 260          // padded row stride (floats) -> conflict-free LDS.128
#define CS 8              // cluster size

__device__ __forceinline__ void cluster_sync_all()
{
    asm volatile("barrier.cluster.arrive.aligned;" ::: "memory");
    asm volatile("barrier.cluster.wait.aligned;" ::: "memory");
}

__device__ __forceinline__ void st_cluster_all(float* localAddr, float val)
{
    unsigned l = (unsigned)__cvta_generic_to_shared(localAddr);
#pragma unroll
    for (int r = 0; r < CS; r++) {
        unsigned rem;
        asm volatile("mapa.shared::cluster.u32 %0, %1, %2;" : "=r"(rem) : "r"(l), "r"(r));
        asm volatile("st.shared::cluster.f32 [%0], %1;" :: "r"(rem), "f"(val) : "memory");
    }
}

extern "C" __global__ void __cluster_dims__(CS, 1, 1) __launch_bounds__(256, 1)
gru_rec(const float* __restrict__ gx, const float* __restrict__ Wr,
        const float* __restrict__ Wz, const float* __restrict__ Wh,
        float* __restrict__ hs, float* __restrict__ hlast)
{
    extern __shared__ float smem[];
    float* sU    = smem;                       // [3][32][WSTR]: r,z,h weight slices
    float* hbuf  = sU + 3 * 32 * WSTR;         // [4][WSTR] full h per local batch
    float* rhbuf = hbuf + 4 * WSTR;            // [4][WSTR] full r*h per local batch
    float* sz    = rhbuf + 4 * WSTR;           // [128]     z gate (own dims x batches)

    const int t  = threadIdx.x;
    const int cl = blockIdx.x >> 3;            // cluster id (batch group)
    const int j  = blockIdx.x & 7;             // rank within cluster (dim slice)

    // --- load weight slices: rows 32j..32j+32, h-columns [256,512) ---
    for (int idx = t; idx < 3 * 32 * 64; idx += 256) {
        int g  = idx / (32 * 64);
        int rm = idx - g * (32 * 64);
        int d  = rm >> 6;
        int kq = rm & 63;
        const float* Wg = (g == 0) ? Wr : (g == 1 ? Wz : Wh);
        float4 v = *(const float4*)(Wg + (size_t)(j * 32 + d) * IH + 256 + kq * 4);
        float* dst = sU + (g * 32 + d) * WSTR + kq * 4;
        dst[0] = v.x; dst[1] = v.y; dst[2] = v.z; dst[3] = v.w;
    }
    // zero h / rh buffers
    for (int idx = t; idx < 8 * WSTR; idx += 256) hbuf[idx] = 0.f;
    __syncthreads();
    cluster_sync_all();   // everyone's buffers ready before remote writes

    const int b    = t & 3;            // local batch 0..3
    const int d    = (t >> 2) & 31;    // dim within slice
    const int g    = t >> 7;           // 0 = r-gate threads, 1 = z-gate threads
    const int bg   = cl * 4 + b;       // global batch
    const int dimg = j * 32 + d;       // global hidden dim

    const float* Urow  = sU + (g * 32 + d) * WSTR;   // sub-A weight row
    const float* Uhrow = sU + (64 + d) * WSTR;       // sub-B weight row (t<128)
    float* hrow  = hbuf  + b * WSTR;
    float* rhrow = rhbuf + b * WSTR;

    for (int s = 0; s < S; s++) {
        const size_t gxbase = ((size_t)bg * S + s) * G3;
        const float gxa = gx[gxbase + g * 256 + dimg];                    // r or z x-part
        const float gxh = (t < 128) ? gx[gxbase + 512 + dimg] : 0.f;      // htilde x-part

        // ---- sub-A: r and z gates (dot over full h) ----
        float a0 = 0.f, a1 = 0.f, a2 = 0.f, a3 = 0.f;
#pragma unroll 8
        for (int k = 0; k < 256; k += 4) {
            float4 w  = *(const float4*)(Urow + k);
            float4 h4 = *(const float4*)(hrow + k);
            a0 += w.x * h4.x; a1 += w.y * h4.y;
            a2 += w.z * h4.z; a3 += w.w * h4.w;
        }
        float pre  = (a0 + a1) + (a2 + a3) + gxa;
        float gate = 1.f / (1.f + expf(-pre));

        if (g == 0) {
            float rh = gate * hrow[dimg];
            st_cluster_all(rhbuf + b * WSTR + dimg, rh);  // replicate r*h slice
        } else {
            sz[d * 4 + b] = gate;                         // keep z locally
        }
        cluster_sync_all();

        // ---- sub-B: htilde + state update (threads 0..127) ----
        if (t < 128) {
            float c0 = 0.f, c1 = 0.f, c2 = 0.f, c3 = 0.f;
#pragma unroll 8
            for (int k = 0; k < 256; k += 4) {
                float4 w  = *(const float4*)(Uhrow + k);
                float4 h4 = *(const float4*)(rhrow + k);
                c0 += w.x * h4.x; c1 += w.y * h4.y;
                c2 += w.z * h4.z; c3 += w.w * h4.w;
            }
            float htil = tanhf((c0 + c1) + (c2 + c3) + gxh);
            float hold = hrow[dimg];
            float z    = sz[d * 4 + b];
            float hn   = hold + z * (htil - hold);
            st_cluster_all(hbuf + b * WSTR + dimg, hn);   // replicate new h slice
            hs[((size_t)bg * S + s) * H + dimg] = hn;
        }
        cluster_sync_all();
    }

    if (t < 128) hlast[(size_t)bg * H + dimg] = hrow[dimg];
}

// ---------------- launch ------------------------------------------------------
extern "C" void kernel_launch(void* const* d_in, const int* in_sizes, int n_in,
                              void* d_out, int out_size)
{
    const float* x    = (const float*)d_in[0];
    const float* W_r  = (const float*)d_in[1];
    const float* b_r  = (const float*)d_in[2];
    const float* W_z  = (const float*)d_in[3];
    const float* b_z  = (const float*)d_in[4];
    const float* W_h  = (const float*)d_in[5];
    const float* b_h  = (const float*)d_in[6];
    const float* W_fc = (const float*)d_in[7];
    const float* b_fc = (const float*)d_in[8];
    float* out = (float*)d_out;                       // [B][S][O] then [B][H]
    float* hlast = out + (size_t)B * S * O;

    float *gx, *hsp, *Wx, *bx;
    cudaGetSymbolAddress((void**)&gx,  g_gx);
    cudaGetSymbolAddress((void**)&hsp, g_hs);
    cudaGetSymbolAddress((void**)&Wx,  g_Wx);
    cudaGetSymbolAddress((void**)&bx,  g_bx);

    // 1. pack x-part weights + biases
    pack_weights<<<G3, 64>>>(W_r, W_z, W_h, b_r, b_z, b_h);

    // 2. gx = x @ Wx^T + bias   [131072 x 256] @ [256 x 768]
    gemm_bias<<<dim3(NROWS / 128, G3 / 64), 256>>>(x, Wx, bx, gx, G3);

    // 3. sequential recurrence (persistent clustered kernel)
    const int smem_bytes = (3 * 32 * WSTR + 8 * WSTR + 128) * sizeof(float);
    static_assert((3 * 32 * WSTR + 8 * WSTR + 128) * 4 < 227 * 1024, "smem");
    cudaFuncSetAttribute(gru_rec, cudaFuncAttributeMaxDynamicSharedMemorySize, smem_bytes);
    gru_rec<<<128, 256, smem_bytes>>>(gx, W_r, W_z, W_h, hsp, hlast);

    // 4. out = hs @ W_fc^T + b_fc   [131072 x 256] @ [256 x 256]
    gemm_bias<<<dim3(NROWS / 128, O / 64), 256>>>(hsp, W_fc, b_fc, out, O);
}